// round 15
// baseline (speedup 1.0000x reference)
#include <cuda_runtime.h>
#include <cuda_bf16.h>
#include <math.h>
#include <stdint.h>

#define BATCH 4
#define CH    256
#define NTOK  4096
#define INTER 32
// QK scale with log2(e) folded in: scores come out in log2 units -> exp2
#define QSC (0.17677669529663687f * 1.4426950408889634f)

// Scratch (no allocation allowed)
__device__ __nv_bfloat16 g_q[(size_t)BATCH * NTOK * INTER];
__device__ __nv_bfloat16 g_k[(size_t)BATCH * NTOK * INTER];
__device__ __nv_bfloat16 g_v[(size_t)BATCH * NTOK * CH];    // token-major bf16
__device__ uint8_t       g_v8[(size_t)BATCH * CH * NTOK];   // channel-major e4m3
__device__ __nv_bfloat16 g_xb[(size_t)BATCH * CH * NTOK];   // x in bf16
__device__ __nv_bfloat16 g_wt[320 * 256];   // fused [Wq;Wk;Wv], q rows pre-scaled
__device__ float         g_bias[320];

// ---------------------------------------------------------------------------
// ptx helpers
// ---------------------------------------------------------------------------
__device__ __forceinline__ uint32_t smem_u32(const void* p) {
    return (uint32_t)__cvta_generic_to_shared(p);
}
__device__ __forceinline__ void cp16(uint32_t dst, const void* src) {
    asm volatile("cp.async.cg.shared.global [%0], [%1], 16;" :: "r"(dst), "l"(src));
}
__device__ __forceinline__ void ldsm_x4(uint32_t* r, uint32_t a) {
    asm volatile("ldmatrix.sync.aligned.m8n8.x4.shared.b16 {%0,%1,%2,%3}, [%4];"
                 : "=r"(r[0]), "=r"(r[1]), "=r"(r[2]), "=r"(r[3]) : "r"(a));
}
__device__ __forceinline__ void ldsm_x4_t(uint32_t* r, uint32_t a) {
    asm volatile("ldmatrix.sync.aligned.m8n8.x4.trans.shared.b16 {%0,%1,%2,%3}, [%4];"
                 : "=r"(r[0]), "=r"(r[1]), "=r"(r[2]), "=r"(r[3]) : "r"(a));
}
__device__ __forceinline__ void mma_bf16(float* c, const uint32_t* a, uint32_t b0, uint32_t b1) {
    asm volatile(
        "mma.sync.aligned.m16n8k16.row.col.f32.bf16.bf16.f32 "
        "{%0,%1,%2,%3}, {%4,%5,%6,%7}, {%8,%9}, {%0,%1,%2,%3};"
        : "+f"(c[0]), "+f"(c[1]), "+f"(c[2]), "+f"(c[3])
        : "r"(a[0]), "r"(a[1]), "r"(a[2]), "r"(a[3]), "r"(b0), "r"(b1));
}
__device__ __forceinline__ void mma_e4m3(float* c, const uint32_t* a, uint32_t b0, uint32_t b1) {
    asm volatile(
        "mma.sync.aligned.m16n8k32.row.col.f32.e4m3.e4m3.f32 "
        "{%0,%1,%2,%3}, {%4,%5,%6,%7}, {%8,%9}, {%0,%1,%2,%3};"
        : "+f"(c[0]), "+f"(c[1]), "+f"(c[2]), "+f"(c[3])
        : "r"(a[0]), "r"(a[1]), "r"(a[2]), "r"(a[3]), "r"(b0), "r"(b1));
}
__device__ __forceinline__ uint32_t packbf(float lo, float hi) {
    __nv_bfloat162 p = __floats2bfloat162_rn(lo, hi);
    return *(uint32_t*)&p;
}
__device__ __forceinline__ unsigned short fp8x2(float lo, float hi) {
    unsigned short d;
    asm("cvt.rn.satfinite.e4m3x2.f32 %0, %1, %2;" : "=h"(d) : "f"(hi), "f"(lo));
    return d;   // low byte = lo, high byte = hi
}
__device__ __forceinline__ float ex2(float x) {
    float y; asm("ex2.approx.f32 %0, %1;" : "=f"(y) : "f"(x)); return y;
}

// ---------------------------------------------------------------------------
// Stage 0: preconvert weights/bias (blocks 0..79) AND x -> bf16 (blocks 80+)
// ---------------------------------------------------------------------------
__global__ void preconv_kernel(
    const float* __restrict__ x,
    const float* __restrict__ Wq, const float* __restrict__ bq,
    const float* __restrict__ Wk, const float* __restrict__ bk,
    const float* __restrict__ Wv, const float* __restrict__ bv)
{
    if (blockIdx.x < 80) {
        int idx = blockIdx.x * 256 + threadIdx.x;     // 0..20479
        int e0  = idx * 4;
        int o   = e0 >> 8, c = e0 & 255;
        float4 v;
        float scale = 1.f;
        if (o < 32)       { v = *(const float4*)&Wq[o*256 + c]; scale = QSC; }
        else if (o < 64)  { v = *(const float4*)&Wk[(o-32)*256 + c]; }
        else              { v = *(const float4*)&Wv[(o-64)*256 + c]; }
        uint2 u;
        u.x = packbf(v.x * scale, v.y * scale);
        u.y = packbf(v.z * scale, v.w * scale);
        *(uint2*)&g_wt[o*256 + c] = u;
        if (idx < 320)
            g_bias[idx] = (idx < 32) ? bq[idx]*QSC : (idx < 64 ? bk[idx-32] : bv[idx-64]);
    } else {
        size_t e0 = ((size_t)(blockIdx.x - 80) * 256 + threadIdx.x) * 8;
        float4 a = *(const float4*)(x + e0);
        float4 c = *(const float4*)(x + e0 + 4);
        uint4 u;
        u.x = packbf(a.x, a.y); u.y = packbf(a.z, a.w);
        u.z = packbf(c.x, c.y); u.w = packbf(c.z, c.w);
        *(uint4*)&g_xb[e0] = u;
    }
}

// ---------------------------------------------------------------------------
// Stage 1: QKV projection, bf16 tensor cores, cp.async-staged x.
// smem bf16: xs[2][32][72] | ws[2][320][40]
// ---------------------------------------------------------------------------
#define XS_STR 72
#define WS_STR 40
#define QOFF_X0 0
#define QOFF_X1 2304
#define QOFF_W0 4608
#define QOFF_W1 17408
#define QKV_SMEM_BF 30208
#define QKV_SMEM_BYTES (QKV_SMEM_BF * 2)   // 60416

__global__ __launch_bounds__(256, 2) void qkv_kernel()
{
    extern __shared__ __align__(16) __nv_bfloat16 smb[];
    const int t    = threadIdx.x;
    const int lane = t & 31;
    const int w    = t >> 5;
    const int g    = lane >> 2;
    const int tg   = lane & 3;
    const int wq   = w & 3;
    const int oh   = (w >> 2) * 160;
    const int b    = blockIdx.y;
    const int n0   = blockIdx.x * 64;

    const uint32_t xs_u[2] = { smem_u32(smb + QOFF_X0), smem_u32(smb + QOFF_X1) };
    const uint32_t ws_u[2] = { smem_u32(smb + QOFF_W0), smem_u32(smb + QOFF_W1) };

    auto stage = [&](int s, int ch0) {
        {
            int row = t >> 3, ck = t & 7;
            cp16(xs_u[s] + (uint32_t)(row*XS_STR + ck*8)*2,
                 g_xb + ((size_t)(b*CH + ch0 + row) * NTOK) + n0 + ck*8);
        }
        #pragma unroll
        for (int i = 0; i < 5; i++) {
            int e = t + i*256;
            int row = e >> 2, seg = (e & 3) * 8;
            cp16(ws_u[s] + (uint32_t)(row*WS_STR + seg)*2,
                 g_wt + row*256 + ch0 + seg);
        }
        asm volatile("cp.async.commit_group;" ::: "memory");
    };

    float acc[20][4];
    #pragma unroll
    for (int nt = 0; nt < 20; nt++)
        #pragma unroll
        for (int k = 0; k < 4; k++) acc[nt][k] = 0.f;

    stage(0, 0);
    asm volatile("cp.async.wait_group 0;" ::: "memory");
    __syncthreads();

    for (int ks = 0; ks < 8; ks++) {
        const int s = ks & 1;
        if (ks < 7) stage(s ^ 1, (ks+1)*32);

        uint32_t qa[2][4];
        #pragma unroll
        for (int kt = 0; kt < 2; kt++) {
            int chr = kt*16 + (lane & 7) + ((lane >> 4) & 1) * 8;
            int tok = wq*16 + ((lane >> 3) & 1) * 8;
            ldsm_x4_t(qa[kt], xs_u[s] + (uint32_t)(chr*XS_STR + tok)*2);
        }
        #pragma unroll
        for (int nt = 0; nt < 20; nt++) {
            uint32_t kb[4];
            int row = oh + nt*8 + (lane & 7);
            int col = (lane >> 3) * 8;
            ldsm_x4(kb, ws_u[s] + (uint32_t)(row*WS_STR + col)*2);
            mma_bf16(acc[nt], qa[0], kb[0], kb[1]);
            mma_bf16(acc[nt], qa[1], kb[2], kb[3]);
        }
        if (ks < 7)
            asm volatile("cp.async.wait_group 0;" ::: "memory");
        __syncthreads();
    }

    int n_lo = n0 + wq*16 + g;
    #pragma unroll
    for (int nt = 0; nt < 20; nt++) {
        int o = oh + nt*8 + 2*tg;
        float b0 = g_bias[o], b1 = g_bias[o+1];
        uint32_t lo = packbf(acc[nt][0] + b0, acc[nt][1] + b1);
        uint32_t hi = packbf(acc[nt][2] + b0, acc[nt][3] + b1);
        __nv_bfloat16* dst; int ldo, oc;
        if (o < 32)      { dst = g_q; ldo = INTER; oc = o; }
        else if (o < 64) { dst = g_k; ldo = INTER; oc = o - 32; }
        else             { dst = g_v; ldo = CH;    oc = o - 64; }
        dst += (size_t)b * NTOK * ldo;
        *(uint32_t*)&dst[(size_t)(n_lo    ) * ldo + oc] = lo;
        *(uint32_t*)&dst[(size_t)(n_lo + 8) * ldo + oc] = hi;
    }
}

// ---------------------------------------------------------------------------
// Stage 1.5: V bf16 token-major -> e4m3 channel-major
// ---------------------------------------------------------------------------
__global__ __launch_bounds__(256) void transv8_kernel()
{
    __shared__ uint8_t ts[64][72];   // [c][n]
    const int b = blockIdx.z, c0 = blockIdx.y * 64, n0 = blockIdx.x * 64;
    const int t = threadIdx.x;

    #pragma unroll
    for (int i = 0; i < 2; i++) {
        int e = t + i*256;
        int nrow = e >> 3, cseg = (e & 7) * 8;
        uint4 u = *(const uint4*)(g_v + ((size_t)(b*NTOK + n0 + nrow) * CH) + c0 + cseg);
        const uint32_t* wp = (const uint32_t*)&u;
        #pragma unroll
        for (int k = 0; k < 4; k++) {
            float2 f = __bfloat1622float2(*(const __nv_bfloat162*)&wp[k]);
            unsigned short pp = fp8x2(f.x, f.y);
            ts[cseg + 2*k    ][nrow] = (uint8_t)(pp & 0xff);
            ts[cseg + 2*k + 1][nrow] = (uint8_t)(pp >> 8);
        }
    }
    __syncthreads();
    {
        int row = t >> 2, seg = (t & 3) * 16;
        uint2 lo = *(const uint2*)&ts[row][seg];
        uint2 hi = *(const uint2*)&ts[row][seg + 8];
        uint4 o; o.x = lo.x; o.y = lo.y; o.z = hi.x; o.w = hi.y;
        *(uint4*)(g_v8 + ((size_t)(b*CH + c0 + row) * NTOK) + n0 + seg) = o;
    }
}

// ---------------------------------------------------------------------------
// Stage 2: flash attention, fp8 PV — 256 threads / Q-tile 64 / 2 CTAs per SM.
// Cross-CTA overlap hides the softmax phase (one CTA's exp under the other's
// PV MMAs). r13-proven serial phase chain + sync ordering per CTA:
//   sync[A] -> restage s^1 -> wait -> sync[V] -> QK/exp/P -> pair bar -> PV.
// Warp w (0..7): i-tile (w&3)*16; half = w>>2: j-half 32 (QK), ch-half 128 (PV).
// smem bytes: Q[64][80] | K[2][64][80] | V[2][256][80] | P[64][80] | lsum f32
// epilogue reuses base smem as ot[256][68] f32 (69632 B); lsum sits beyond it.
// ---------------------------------------------------------------------------
#define OFFQ 0
#define OFFK 5120
#define OFFV 15360
#define OFFP 56320
#define OFFL 69632
#define KBUFB 5120
#define VBUFB 20480
#define ATT_SMEM_BYTES 70144

__global__ __launch_bounds__(256, 2) void attn_kernel(
    const float* __restrict__ x, const float* __restrict__ gamma_p,
    float* __restrict__ out)
{
    extern __shared__ __align__(16) char smc[];
    float* lsum = (float*)(smc + OFFL);

    const int t    = threadIdx.x;
    const int lane = t & 31;
    const int w    = t >> 5;        // 0..7
    const int g    = lane >> 2;
    const int tg   = lane & 3;
    const int iw   = w & 3;
    const int ib   = iw * 16;       // i-tile base (0..48)
    const int half = w >> 2;
    const int cb   = half * 128;    // channel half for PV
    const int jh   = half * 32;     // j-half for QK/exp
    const int b    = blockIdx.y;
    const int i0   = blockIdx.x * 64;

    const uint32_t u_q = smem_u32(smc) + OFFQ;
    const uint32_t u_k = smem_u32(smc) + OFFK;
    const uint32_t u_v = smem_u32(smc) + OFFV;
    const uint32_t u_p = smem_u32(smc) + OFFP;

    auto stage = [&](int s, int j0) {
        {   // K tile [64][32] bf16 (80B rows): 256 cp16
            int row = t >> 2, c = t & 3;
            cp16(u_k + s*KBUFB + row*80 + c*16,
                 g_k + ((size_t)(b*NTOK + j0 + row) * INTER) + c*8);
        }
        #pragma unroll
        for (int i = 0; i < 4; i++) {   // V tile fp8 [256 ch][64 j]: 1024 cp16
            int e = t + i*256;
            int row = e >> 2, ch = (e & 3) * 16;
            cp16(u_v + s*VBUFB + row*80 + ch,
                 g_v8 + ((size_t)(b*CH + row) * NTOK) + j0 + ch);
        }
        asm volatile("cp.async.commit_group;" ::: "memory");
    };

    {   // prologue: Q [64][32] bf16 (one group), then tile 0
        int row = t >> 2, c = t & 3;
        cp16(u_q + row*80 + c*16,
             g_q + ((size_t)(b*NTOK + i0 + row) * INTER) + c*8);
        asm volatile("cp.async.commit_group;" ::: "memory");
    }
    stage(0, 0);
    asm volatile("cp.async.wait_group 1;" ::: "memory");   // Q landed
    __syncthreads();                                       // Q visible

    uint32_t qa[2][4];
    #pragma unroll
    for (int kt = 0; kt < 2; kt++) {
        int row = ib + (lane & 7) + ((lane >> 3) & 1) * 8;
        int col = kt*16 + ((lane >> 4) & 1) * 8;
        ldsm_x4(qa[kt], u_q + row*80 + col*2);
    }

    // hoisted ldmatrix base offsets
    const uint32_t pa_off = (uint32_t)(ib + 8*((lane >> 3) & 1) + (lane & 7))*80
                          + ((lane >> 4) & 1)*16;
    const uint32_t vb_row = (uint32_t)(cb + ((lane >> 4) & 1)*8 + (lane & 7));
    const uint32_t vb_off = vb_row*80 + ((lane >> 3) & 1)*16;

    float acc[16][4];
    #pragma unroll
    for (int nt = 0; nt < 16; nt++)
        #pragma unroll
        for (int k = 0; k < 4; k++) acc[nt][k] = 0.f;
    float l0 = 0.f, l1 = 0.f;

    for (int jt = 0; jt < 64; jt++) {
        const int s = jt & 1;

        __syncthreads();   // [A] prev iter fully done: buf s^1 and P free
        if (jt < 63) {
            stage(s ^ 1, (jt + 1) * 64);
            asm volatile("cp.async.wait_group 1;" ::: "memory");  // buf s landed
        } else {
            asm volatile("cp.async.wait_group 0;" ::: "memory");
        }
        __syncthreads();   // [V] buf s visible to ALL threads

        const uint32_t k_u = u_k + s*KBUFB;
        const uint32_t v_b = u_v + s*VBUFB + vb_off;

        // ---- QK^T on this warp's j-half: S[16][32] (log2 units), bf16 ----
        float sfr[4][4];
        #pragma unroll
        for (int j8 = 0; j8 < 4; j8++) {
            sfr[j8][0] = sfr[j8][1] = sfr[j8][2] = sfr[j8][3] = 0.f;
            uint32_t kb[4];
            int row = jh + j8*8 + (lane & 7);
            int col = (lane >> 3) * 8;
            ldsm_x4(kb, k_u + row*80 + col*2);
            mma_bf16(sfr[j8], qa[0], kb[0], kb[1]);
            mma_bf16(sfr[j8], qa[1], kb[2], kb[3]);
        }

        // ---- exp2, accumulate l, store P (e4m3) ----
        #pragma unroll
        for (int j8 = 0; j8 < 4; j8++) {
            float p0 = ex2(sfr[j8][0]), p1 = ex2(sfr[j8][1]);
            float p2 = ex2(sfr[j8][2]), p3 = ex2(sfr[j8][3]);
            l0 += p0 + p1;
            l1 += p2 + p3;
            unsigned short lo = fp8x2(p0, p1);
            unsigned short hi = fp8x2(p2, p3);
            int col = jh + j8*8 + 2*tg;
            asm volatile("st.shared.u16 [%0], %1;"
                :: "r"(u_p + (ib + g    )*80 + col), "h"(lo) : "memory");
            asm volatile("st.shared.u16 [%0], %1;"
                :: "r"(u_p + (ib + 8 + g)*80 + col), "h"(hi) : "memory");
        }

        // [B] pair barrier: warps {iw, iw+4} both finished their P half.
        asm volatile("bar.sync %0, 64;" :: "r"(1 + iw) : "memory");

        // ---- PV (e4m3 m16n8k32), ldmatrix-fed:
        //      O[16][128] += P[16][64] x V[64][128] ----
        #pragma unroll
        for (int kt = 0; kt < 2; kt++) {
            uint32_t pa[4];
            ldsm_x4(pa, u_p + pa_off + kt*32);
            #pragma unroll
            for (int nb = 0; nb < 8; nb++) {
                uint32_t vb[4];
                ldsm_x4(vb, v_b + (uint32_t)(nb*16)*80 + kt*32);
                mma_e4m3(acc[2*nb    ], pa, vb[0], vb[1]);
                mma_e4m3(acc[2*nb + 1], pa, vb[2], vb[3]);
            }
        }
    }

    // ---- combine l across quad lanes + across j-half warps ----
    l0 += __shfl_xor_sync(0xffffffffu, l0, 1);
    l0 += __shfl_xor_sync(0xffffffffu, l0, 2);
    l1 += __shfl_xor_sync(0xffffffffu, l1, 1);
    l1 += __shfl_xor_sync(0xffffffffu, l1, 2);
    if (tg == 0) {
        lsum[(ib + g    )*2 + half] = l0;
        lsum[(ib + 8 + g)*2 + half] = l1;
    }
    __syncthreads();
    float li0 = 1.f / (lsum[(ib + g    )*2] + lsum[(ib + g    )*2 + 1]);
    float li1 = 1.f / (lsum[(ib + 8 + g)*2] + lsum[(ib + 8 + g)*2 + 1]);
    #pragma unroll
    for (int nt = 0; nt < 16; nt++) {
        acc[nt][0] *= li0; acc[nt][1] *= li0;
        acc[nt][2] *= li1; acc[nt][3] *= li1;
    }

    // ---- epilogue: smem transpose, then coalesced residual store ----
    const float gmm = gamma_p[0];
    float (*ot)[68] = (float (*)[68])smc;   // [256][68] f32 = 69632 B; lsum beyond
    #pragma unroll
    for (int nt = 0; nt < 16; nt++) {
        int c = cb + nt*8 + 2*tg;
        int i = ib + g;
        ot[c  ][i  ] = acc[nt][0];
        ot[c+1][i  ] = acc[nt][1];
        ot[c  ][i+8] = acc[nt][2];
        ot[c+1][i+8] = acc[nt][3];
    }
    __syncthreads();
    {
        int c = t;   // one channel per thread, 64 tokens = 16 float4
        size_t base = ((size_t)(b*CH + c)) * NTOK + i0;
        const float4* xp = (const float4*)(x + base);
        float4* op = (float4*)(out + base);
        #pragma unroll
        for (int i4 = 0; i4 < 16; i4++) {
            float4 xv = xp[i4];
            float4 r4;
            r4.x = gmm * ot[c][i4*4 + 0] + xv.x;
            r4.y = gmm * ot[c][i4*4 + 1] + xv.y;
            r4.z = gmm * ot[c][i4*4 + 2] + xv.z;
            r4.w = gmm * ot[c][i4*4 + 3] + xv.w;
            op[i4] = r4;
        }
    }
}

// ---------------------------------------------------------------------------
extern "C" void kernel_launch(void* const* d_in, const int* in_sizes, int n_in,
                              void* d_out, int out_size)
{
    const float* x  = (const float*)d_in[0];
    const float* Wq = (const float*)d_in[1];
    const float* bq = (const float*)d_in[2];
    const float* Wk = (const float*)d_in[3];
    const float* bk = (const float*)d_in[4];
    const float* Wv = (const float*)d_in[5];
    const float* bv = (const float*)d_in[6];
    const float* gm = (const float*)d_in[7];
    float* out = (float*)d_out;

    cudaFuncSetAttribute(qkv_kernel,  cudaFuncAttributeMaxDynamicSharedMemorySize, QKV_SMEM_BYTES);
    cudaFuncSetAttribute(attn_kernel, cudaFuncAttributeMaxDynamicSharedMemorySize, ATT_SMEM_BYTES);

    preconv_kernel<<<80 + 2048, 256>>>(x, Wq, bq, Wk, bk, Wv, bv);

    dim3 g1(NTOK / 64, BATCH);
    qkv_kernel<<<g1, 256, QKV_SMEM_BYTES>>>();

    dim3 gt(NTOK / 64, CH / 64, BATCH);
    transv8_kernel<<<gt, 256>>>();

    dim3 g2(NTOK / 64, BATCH);
    attn_kernel<<<g2, 256, ATT_SMEM_BYTES>>>(x, gm, out);
}

// round 16
// speedup vs baseline: 1.0666x; 1.0666x over previous
#include <cuda_runtime.h>
#include <cuda_bf16.h>
#include <math.h>
#include <stdint.h>

#define BATCH 4
#define CH    256
#define NTOK  4096
#define INTER 32
// QK scale with log2(e) folded in: scores come out in log2 units -> exp2
#define QSC (0.17677669529663687f * 1.4426950408889634f)

// Scratch (no allocation allowed)
__device__ __nv_bfloat16 g_q[(size_t)BATCH * NTOK * INTER];
__device__ __nv_bfloat16 g_k[(size_t)BATCH * NTOK * INTER];
__device__ __nv_bfloat16 g_v[(size_t)BATCH * NTOK * CH];
__device__ __nv_bfloat16 g_xb[(size_t)BATCH * CH * NTOK];   // x in bf16
__device__ __nv_bfloat16 g_wt[320 * 256];   // fused [Wq;Wk;Wv], q rows pre-scaled
__device__ float         g_bias[320];

// ---------------------------------------------------------------------------
// ptx helpers
// ---------------------------------------------------------------------------
__device__ __forceinline__ uint32_t smem_u32(const void* p) {
    return (uint32_t)__cvta_generic_to_shared(p);
}
__device__ __forceinline__ void cp16(uint32_t dst, const void* src) {
    asm volatile("cp.async.cg.shared.global [%0], [%1], 16;" :: "r"(dst), "l"(src));
}
__device__ __forceinline__ void ldsm_x4(uint32_t* r, uint32_t a) {
    asm volatile("ldmatrix.sync.aligned.m8n8.x4.shared.b16 {%0,%1,%2,%3}, [%4];"
                 : "=r"(r[0]), "=r"(r[1]), "=r"(r[2]), "=r"(r[3]) : "r"(a));
}
__device__ __forceinline__ void ldsm_x4_t(uint32_t* r, uint32_t a) {
    asm volatile("ldmatrix.sync.aligned.m8n8.x4.trans.shared.b16 {%0,%1,%2,%3}, [%4];"
                 : "=r"(r[0]), "=r"(r[1]), "=r"(r[2]), "=r"(r[3]) : "r"(a));
}
__device__ __forceinline__ void mma_bf16(float* c, const uint32_t* a, uint32_t b0, uint32_t b1) {
    asm volatile(
        "mma.sync.aligned.m16n8k16.row.col.f32.bf16.bf16.f32 "
        "{%0,%1,%2,%3}, {%4,%5,%6,%7}, {%8,%9}, {%0,%1,%2,%3};"
        : "+f"(c[0]), "+f"(c[1]), "+f"(c[2]), "+f"(c[3])
        : "r"(a[0]), "r"(a[1]), "r"(a[2]), "r"(a[3]), "r"(b0), "r"(b1));
}
__device__ __forceinline__ uint32_t packbf(float lo, float hi) {
    __nv_bfloat162 p = __floats2bfloat162_rn(lo, hi);
    return *(uint32_t*)&p;
}
__device__ __forceinline__ float ex2(float x) {
    float y; asm("ex2.approx.f32 %0, %1;" : "=f"(y) : "f"(x)); return y;
}

// ---------------------------------------------------------------------------
// Stage 0: preconvert weights/bias (blocks 0..79) AND x -> bf16 (blocks 80+)
// ---------------------------------------------------------------------------
__global__ void preconv_kernel(
    const float* __restrict__ x,
    const float* __restrict__ Wq, const float* __restrict__ bq,
    const float* __restrict__ Wk, const float* __restrict__ bk,
    const float* __restrict__ Wv, const float* __restrict__ bv)
{
    if (blockIdx.x < 80) {
        int idx = blockIdx.x * 256 + threadIdx.x;     // 0..20479
        int e0  = idx * 4;
        int o   = e0 >> 8, c = e0 & 255;
        float4 v;
        float scale = 1.f;
        if (o < 32)       { v = *(const float4*)&Wq[o*256 + c]; scale = QSC; }
        else if (o < 64)  { v = *(const float4*)&Wk[(o-32)*256 + c]; }
        else              { v = *(const float4*)&Wv[(o-64)*256 + c]; }
        uint2 u;
        u.x = packbf(v.x * scale, v.y * scale);
        u.y = packbf(v.z * scale, v.w * scale);
        *(uint2*)&g_wt[o*256 + c] = u;
        if (idx < 320)
            g_bias[idx] = (idx < 32) ? bq[idx]*QSC : (idx < 64 ? bk[idx-32] : bv[idx-64]);
    } else {
        size_t e0 = ((size_t)(blockIdx.x - 80) * 256 + threadIdx.x) * 8;
        float4 a = *(const float4*)(x + e0);
        float4 c = *(const float4*)(x + e0 + 4);
        uint4 u;
        u.x = packbf(a.x, a.y); u.y = packbf(a.z, a.w);
        u.z = packbf(c.x, c.y); u.w = packbf(c.z, c.w);
        *(uint4*)&g_xb[e0] = u;
    }
}

// ---------------------------------------------------------------------------
// Stage 1: QKV projection, bf16 tensor cores, cp.async-staged x.
// Mainloop = r11 (proven). Epilogue reworked: smem transpose -> fully
// coalesced uint4 stores (was 40 scattered 4B STG per thread).
// smem bf16: xs[2][32][72] | ws[2][320][40]; epilogue reuses as os[64][328]
// ---------------------------------------------------------------------------
#define XS_STR 72
#define WS_STR 40
#define OS_STR 328
#define QOFF_X0 0
#define QOFF_X1 2304
#define QOFF_W0 4608
#define QOFF_W1 17408
#define QKV_SMEM_BF 30208
#define QKV_SMEM_BYTES (QKV_SMEM_BF * 2)   // 60416 (os needs 41984 B: fits)

__global__ __launch_bounds__(256, 2) void qkv_kernel()
{
    extern __shared__ __align__(16) __nv_bfloat16 smb[];
    const int t    = threadIdx.x;
    const int lane = t & 31;
    const int w    = t >> 5;
    const int g    = lane >> 2;
    const int tg   = lane & 3;
    const int wq   = w & 3;
    const int oh   = (w >> 2) * 160;
    const int b    = blockIdx.y;
    const int n0   = blockIdx.x * 64;

    const uint32_t xs_u[2] = { smem_u32(smb + QOFF_X0), smem_u32(smb + QOFF_X1) };
    const uint32_t ws_u[2] = { smem_u32(smb + QOFF_W0), smem_u32(smb + QOFF_W1) };

    auto stage = [&](int s, int ch0) {
        {
            int row = t >> 3, ck = t & 7;
            cp16(xs_u[s] + (uint32_t)(row*XS_STR + ck*8)*2,
                 g_xb + ((size_t)(b*CH + ch0 + row) * NTOK) + n0 + ck*8);
        }
        #pragma unroll
        for (int i = 0; i < 5; i++) {
            int e = t + i*256;
            int row = e >> 2, seg = (e & 3) * 8;
            cp16(ws_u[s] + (uint32_t)(row*WS_STR + seg)*2,
                 g_wt + row*256 + ch0 + seg);
        }
        asm volatile("cp.async.commit_group;" ::: "memory");
    };

    float acc[20][4];
    #pragma unroll
    for (int nt = 0; nt < 20; nt++)
        #pragma unroll
        for (int k = 0; k < 4; k++) acc[nt][k] = 0.f;

    stage(0, 0);
    asm volatile("cp.async.wait_group 0;" ::: "memory");
    __syncthreads();

    for (int ks = 0; ks < 8; ks++) {
        const int s = ks & 1;
        if (ks < 7) stage(s ^ 1, (ks+1)*32);

        uint32_t qa[2][4];
        #pragma unroll
        for (int kt = 0; kt < 2; kt++) {
            int chr = kt*16 + (lane & 7) + ((lane >> 4) & 1) * 8;
            int tok = wq*16 + ((lane >> 3) & 1) * 8;
            ldsm_x4_t(qa[kt], xs_u[s] + (uint32_t)(chr*XS_STR + tok)*2);
        }
        #pragma unroll
        for (int nt = 0; nt < 20; nt++) {
            uint32_t kb[4];
            int row = oh + nt*8 + (lane & 7);
            int col = (lane >> 3) * 8;
            ldsm_x4(kb, ws_u[s] + (uint32_t)(row*WS_STR + col)*2);
            mma_bf16(acc[nt], qa[0], kb[0], kb[1]);
            mma_bf16(acc[nt], qa[1], kb[2], kb[3]);
        }
        if (ks < 7)
            asm volatile("cp.async.wait_group 0;" ::: "memory");
        __syncthreads();
    }

    // ---- epilogue: bias, transpose through smem, coalesced stores ----
    __syncthreads();   // mainloop smem fully consumed
    {
        int tok0 = wq*16 + g;
        #pragma unroll
        for (int nt = 0; nt < 20; nt++) {
            int o = oh + nt*8 + 2*tg;
            float b0 = g_bias[o], b1 = g_bias[o+1];
            *(uint32_t*)&smb[tok0*OS_STR + o] =
                packbf(acc[nt][0] + b0, acc[nt][1] + b1);
            *(uint32_t*)&smb[(tok0 + 8)*OS_STR + o] =
                packbf(acc[nt][2] + b0, acc[nt][3] + b1);
        }
    }
    __syncthreads();
    {
        __nv_bfloat16* qd = g_q + (size_t)b * NTOK * INTER;
        __nv_bfloat16* kd = g_k + (size_t)b * NTOK * INTER;
        __nv_bfloat16* vd = g_v + (size_t)b * NTOK * CH;
        #pragma unroll
        for (int i = 0; i < 10; i++) {
            int e = t + i*256;        // 0..2559
            int tok = e / 40, slot = e % 40;
            uint4 val = *(const uint4*)&smb[tok*OS_STR + slot*8];
            int n = n0 + tok;
            if (slot < 4)
                *(uint4*)&qd[(size_t)n*INTER + slot*8] = val;
            else if (slot < 8)
                *(uint4*)&kd[(size_t)n*INTER + (slot-4)*8] = val;
            else
                *(uint4*)&vd[(size_t)n*CH + (slot-8)*8] = val;
        }
    }
}

// ---------------------------------------------------------------------------
// Stage 2: bf16 TC flash attention (exact r7 / 178.8us version).
// Q-tile 128, 512 threads, 16 warps; j-tile 64, double-buffered.
// Per iter: sync (prev done) -> restage s^1 -> wait -> sync (s visible)
//           -> QK/exp/P -> pair bar -> PV.
// smem bf16: Q[128][40] | K[2][64][40] | V[2][64][264] | P[128][72] | lsum f32
// ---------------------------------------------------------------------------
#define SQB 40
#define SVB 264
#define SPB 72
#define OFFQ 0
#define OFFK 5120
#define OFFV 10240
#define OFFP 44032
#define KBUF 2560
#define VBUF 16896
#define ATT_SMEM_BF 53248
#define ATT_SMEM_BYTES (ATT_SMEM_BF*2 + 1024)   // 107520

__global__ __launch_bounds__(512, 1) void attn_kernel(
    const float* __restrict__ x, const float* __restrict__ gamma_p,
    float* __restrict__ out)
{
    extern __shared__ __align__(16) __nv_bfloat16 smb[];
    float* lsum = (float*)(smb + ATT_SMEM_BF);

    const int t    = threadIdx.x;
    const int lane = t & 31;
    const int w    = t >> 5;        // 0..15
    const int g    = lane >> 2;
    const int tg   = lane & 3;
    const int iw   = w & 7;
    const int ib   = iw * 16;       // i-tile base (0..112)
    const int half = w >> 3;
    const int cb   = half * 128;
    const int jh   = half * 32;
    const int b    = blockIdx.y;
    const int i0   = blockIdx.x * 128;

    const uint32_t q_u  = smem_u32(smb + OFFQ);
    const uint32_t k_u0 = smem_u32(smb + OFFK);
    const uint32_t v_u0 = smem_u32(smb + OFFV);
    const uint32_t p_u  = smem_u32(smb + OFFP);

    auto stage = [&](int s, int j0) {
        if (t < 256) {   // K tile [64][32]
            int row = t >> 2, c = t & 3;
            cp16(k_u0 + (uint32_t)(s*KBUF + row*SQB + c*8)*2,
                 g_k + ((size_t)(b*NTOK + j0 + row) * INTER) + c*8);
        }
        {   // V tile [64][256]: row = t>>3, 4 cp16 each
            int row = t >> 3, cs = t & 7;
            const __nv_bfloat16* vsrc = g_v + ((size_t)(b*NTOK + j0 + row) * CH);
            uint32_t vdst = v_u0 + (uint32_t)(s*VBUF + row*SVB)*2;
            #pragma unroll
            for (int k = 0; k < 4; k++) {
                int ch = (cs + 8*k) * 8;
                cp16(vdst + ch*2, vsrc + ch);
            }
        }
        asm volatile("cp.async.commit_group;" ::: "memory");
    };

    {   // prologue: Q [128][32] (one group), then tile 0
        int row = t >> 2, c = t & 3;
        cp16(q_u + (uint32_t)(row*SQB + c*8)*2,
             g_q + ((size_t)(b*NTOK + i0 + row) * INTER) + c*8);
        asm volatile("cp.async.commit_group;" ::: "memory");
    }
    stage(0, 0);
    asm volatile("cp.async.wait_group 1;" ::: "memory");   // Q landed
    __syncthreads();                                       // Q visible

    uint32_t qa[2][4];
    #pragma unroll
    for (int kt = 0; kt < 2; kt++) {
        int row = ib + (lane & 7) + ((lane >> 3) & 1) * 8;
        int col = kt*16 + ((lane >> 4) & 1) * 8;
        ldsm_x4(qa[kt], q_u + (uint32_t)(row*SQB + col)*2);
    }

    float acc[16][4];
    #pragma unroll
    for (int nt = 0; nt < 16; nt++)
        #pragma unroll
        for (int k = 0; k < 4; k++) acc[nt][k] = 0.f;
    float l0 = 0.f, l1 = 0.f;

    for (int jt = 0; jt < 64; jt++) {
        const int s = jt & 1;

        __syncthreads();   // [A] prev iter fully done: buf s^1 and P free
        if (jt < 63) {
            stage(s ^ 1, (jt + 1) * 64);
            asm volatile("cp.async.wait_group 1;" ::: "memory");  // buf s landed
        } else {
            asm volatile("cp.async.wait_group 0;" ::: "memory");
        }
        __syncthreads();   // [V] buf s visible to ALL threads

        const uint32_t k_u = k_u0 + (uint32_t)(s*KBUF)*2;
        const uint32_t v_u = v_u0 + (uint32_t)(s*VBUF)*2;

        // ---- QK^T on this warp's j-half: S[16][32] (log2 units) ----
        float sfr[4][4];
        #pragma unroll
        for (int j8 = 0; j8 < 4; j8++) {
            sfr[j8][0] = sfr[j8][1] = sfr[j8][2] = sfr[j8][3] = 0.f;
            uint32_t kb[4];
            int row = jh + j8*8 + (lane & 7);
            int col = (lane >> 3) * 8;
            ldsm_x4(kb, k_u + (uint32_t)(row*SQB + col)*2);
            mma_bf16(sfr[j8], qa[0], kb[0], kb[1]);
            mma_bf16(sfr[j8], qa[1], kb[2], kb[3]);
        }

        // ---- exp2, accumulate l, store P (bf16) ----
        #pragma unroll
        for (int j8 = 0; j8 < 4; j8++) {
            float p0 = ex2(sfr[j8][0]), p1 = ex2(sfr[j8][1]);
            float p2 = ex2(sfr[j8][2]), p3 = ex2(sfr[j8][3]);
            l0 += p0 + p1;
            l1 += p2 + p3;
            int col = jh + j8*8 + 2*tg;
            *(uint32_t*)(smb + OFFP + (ib + g    )*SPB + col) = packbf(p0, p1);
            *(uint32_t*)(smb + OFFP + (ib + 8 + g)*SPB + col) = packbf(p2, p3);
        }

        // [B] pair barrier: warps {iw, iw+8} both finished their P half.
        asm volatile("bar.sync %0, 64;" :: "r"(1 + iw) : "memory");

        // ---- PV: O[16][128] += P[16][64] x V[64][128] ----
        #pragma unroll
        for (int kt = 0; kt < 4; kt++) {
            uint32_t pa[4];
            {
                int row = ib + (lane & 7) + ((lane >> 3) & 1) * 8;
                int col = kt*16 + ((lane >> 4) & 1) * 8;
                ldsm_x4(pa, p_u + (uint32_t)(row*SPB + col)*2);
            }
            #pragma unroll
            for (int np = 0; np < 8; np++) {
                uint32_t vb[4];
                int row = kt*16 + ((lane >> 3) & 1)*8 + (lane & 7);
                int col = cb + (np*2 + (lane >> 4)) * 8;
                ldsm_x4_t(vb, v_u + (uint32_t)(row*SVB + col)*2);
                mma_bf16(acc[2*np    ], pa, vb[0], vb[1]);
                mma_bf16(acc[2*np + 1], pa, vb[2], vb[3]);
            }
        }
    }

    // ---- combine l across quad lanes + across j-half warps ----
    l0 += __shfl_xor_sync(0xffffffffu, l0, 1);
    l0 += __shfl_xor_sync(0xffffffffu, l0, 2);
    l1 += __shfl_xor_sync(0xffffffffu, l1, 1);
    l1 += __shfl_xor_sync(0xffffffffu, l1, 2);
    if (tg == 0) {
        lsum[(ib + g    )*2 + half] = l0;
        lsum[(ib + 8 + g)*2 + half] = l1;
    }
    __syncthreads();
    float li0 = 1.f / (lsum[(ib + g    )*2] + lsum[(ib + g    )*2 + 1]);
    float li1 = 1.f / (lsum[(ib + 8 + g)*2] + lsum[(ib + 8 + g)*2 + 1]);
    #pragma unroll
    for (int nt = 0; nt < 16; nt++) {
        acc[nt][0] *= li0; acc[nt][1] *= li0;
        acc[nt][2] *= li1; acc[nt][3] *= li1;
    }

    // ---- epilogue: two 64-query halves through smem transpose ----
    const float gmm = gamma_p[0];
    float (*ot)[68] = (float (*)[68])smb;   // [256][68] fp32; lsum is beyond
    for (int h = 0; h < 2; h++) {
        __syncthreads();
        if ((iw >> 2) == h) {
            int il = (ib & 63) + g;   // 0..63 within half
            #pragma unroll
            for (int nt = 0; nt < 16; nt++) {
                int c = cb + nt*8 + 2*tg;
                ot[c  ][il  ] = acc[nt][0];
                ot[c+1][il  ] = acc[nt][1];
                ot[c  ][il+8] = acc[nt][2];
                ot[c+1][il+8] = acc[nt][3];
            }
        }
        __syncthreads();
        {   // 512 threads: c = t>>1, token segment (t&1)*32 (8 float4)
            int c = t >> 1, seg = (t & 1) * 32;
            size_t base = ((size_t)(b*CH + c)) * NTOK + i0 + h*64 + seg;
            const float4* xp = (const float4*)(x + base);
            float4* op = (float4*)(out + base);
            #pragma unroll
            for (int i4 = 0; i4 < 8; i4++) {
                float4 xv = xp[i4];
                float4 r4;
                r4.x = gmm * ot[c][seg + i4*4 + 0] + xv.x;
                r4.y = gmm * ot[c][seg + i4*4 + 1] + xv.y;
                r4.z = gmm * ot[c][seg + i4*4 + 2] + xv.z;
                r4.w = gmm * ot[c][seg + i4*4 + 3] + xv.w;
                op[i4] = r4;
            }
        }
    }
}

// ---------------------------------------------------------------------------
extern "C" void kernel_launch(void* const* d_in, const int* in_sizes, int n_in,
                              void* d_out, int out_size)
{
    const float* x  = (const float*)d_in[0];
    const float* Wq = (const float*)d_in[1];
    const float* bq = (const float*)d_in[2];
    const float* Wk = (const float*)d_in[3];
    const float* bk = (const float*)d_in[4];
    const float* Wv = (const float*)d_in[5];
    const float* bv = (const float*)d_in[6];
    const float* gm = (const float*)d_in[7];
    float* out = (float*)d_out;

    cudaFuncSetAttribute(qkv_kernel,  cudaFuncAttributeMaxDynamicSharedMemorySize, QKV_SMEM_BYTES);
    cudaFuncSetAttribute(attn_kernel, cudaFuncAttributeMaxDynamicSharedMemorySize, ATT_SMEM_BYTES);

    preconv_kernel<<<80 + 2048, 256>>>(x, Wq, bq, Wk, bk, Wv, bv);

    dim3 g1(NTOK / 64, BATCH);
    qkv_kernel<<<g1, 256, QKV_SMEM_BYTES>>>();

    dim3 g2(NTOK / 128, BATCH);
    attn_kernel<<<g2, 512, ATT_SMEM_BYTES>>>(x, gm, out);
}

// round 17
// speedup vs baseline: 1.1043x; 1.0353x over previous
#include <cuda_runtime.h>
#include <cuda_bf16.h>
#include <math.h>
#include <stdint.h>

#define BATCH 4
#define CH    256
#define NTOK  4096
#define INTER 32
// QK scale with log2(e) folded in: scores come out in log2 units -> exp2
#define QSC (0.17677669529663687f * 1.4426950408889634f)

// Scratch (no allocation allowed)
__device__ __nv_bfloat16 g_q[(size_t)BATCH * NTOK * INTER];
__device__ __nv_bfloat16 g_k[(size_t)BATCH * NTOK * INTER];
__device__ __nv_bfloat16 g_v[(size_t)BATCH * NTOK * CH];
__device__ __nv_bfloat16 g_xb[(size_t)BATCH * CH * NTOK];   // x in bf16
__device__ __nv_bfloat16 g_wt[320 * 256];   // fused [Wq;Wk;Wv], q rows pre-scaled
__device__ float         g_bias[320];

// ---------------------------------------------------------------------------
// ptx helpers
// ---------------------------------------------------------------------------
__device__ __forceinline__ uint32_t smem_u32(const void* p) {
    return (uint32_t)__cvta_generic_to_shared(p);
}
__device__ __forceinline__ void cp16(uint32_t dst, const void* src) {
    asm volatile("cp.async.cg.shared.global [%0], [%1], 16;" :: "r"(dst), "l"(src));
}
__device__ __forceinline__ void ldsm_x4(uint32_t* r, uint32_t a) {
    asm volatile("ldmatrix.sync.aligned.m8n8.x4.shared.b16 {%0,%1,%2,%3}, [%4];"
                 : "=r"(r[0]), "=r"(r[1]), "=r"(r[2]), "=r"(r[3]) : "r"(a));
}
__device__ __forceinline__ void ldsm_x4_t(uint32_t* r, uint32_t a) {
    asm volatile("ldmatrix.sync.aligned.m8n8.x4.trans.shared.b16 {%0,%1,%2,%3}, [%4];"
                 : "=r"(r[0]), "=r"(r[1]), "=r"(r[2]), "=r"(r[3]) : "r"(a));
}
__device__ __forceinline__ void mma_bf16(float* c, const uint32_t* a, uint32_t b0, uint32_t b1) {
    asm volatile(
        "mma.sync.aligned.m16n8k16.row.col.f32.bf16.bf16.f32 "
        "{%0,%1,%2,%3}, {%4,%5,%6,%7}, {%8,%9}, {%0,%1,%2,%3};"
        : "+f"(c[0]), "+f"(c[1]), "+f"(c[2]), "+f"(c[3])
        : "r"(a[0]), "r"(a[1]), "r"(a[2]), "r"(a[3]), "r"(b0), "r"(b1));
}
__device__ __forceinline__ uint32_t packbf(float lo, float hi) {
    __nv_bfloat162 p = __floats2bfloat162_rn(lo, hi);
    return *(uint32_t*)&p;
}
__device__ __forceinline__ float ex2(float x) {
    float y; asm("ex2.approx.f32 %0, %1;" : "=f"(y) : "f"(x)); return y;
}

// ---------------------------------------------------------------------------
// Stage 0: preconvert weights/bias (blocks 0..79) AND x -> bf16 (blocks 80+)
// ---------------------------------------------------------------------------
__global__ void preconv_kernel(
    const float* __restrict__ x,
    const float* __restrict__ Wq, const float* __restrict__ bq,
    const float* __restrict__ Wk, const float* __restrict__ bk,
    const float* __restrict__ Wv, const float* __restrict__ bv)
{
    if (blockIdx.x < 80) {
        int idx = blockIdx.x * 256 + threadIdx.x;     // 0..20479
        int e0  = idx * 4;
        int o   = e0 >> 8, c = e0 & 255;
        float4 v;
        float scale = 1.f;
        if (o < 32)       { v = *(const float4*)&Wq[o*256 + c]; scale = QSC; }
        else if (o < 64)  { v = *(const float4*)&Wk[(o-32)*256 + c]; }
        else              { v = *(const float4*)&Wv[(o-64)*256 + c]; }
        uint2 u;
        u.x = packbf(v.x * scale, v.y * scale);
        u.y = packbf(v.z * scale, v.w * scale);
        *(uint2*)&g_wt[o*256 + c] = u;
        if (idx < 320)
            g_bias[idx] = (idx < 32) ? bq[idx]*QSC : (idx < 64 ? bk[idx-32] : bv[idx-64]);
    } else {
        size_t e0 = ((size_t)(blockIdx.x - 80) * 256 + threadIdx.x) * 8;
        float4 a = *(const float4*)(x + e0);
        float4 c = *(const float4*)(x + e0 + 4);
        uint4 u;
        u.x = packbf(a.x, a.y); u.y = packbf(a.z, a.w);
        u.z = packbf(c.x, c.y); u.w = packbf(c.z, c.w);
        *(uint4*)&g_xb[e0] = u;
    }
}

// ---------------------------------------------------------------------------
// Stage 1: QKV projection, bf16 tensor cores, cp.async-staged x & W.
// CTA = 128 tokens x 320 outputs, 512 threads, 16 warps:
//   warp w: tok-tile (w&7)*16, out-half (w>>3)*160.
// W staging amortized over 2x tokens vs r11 (the LDGSTS-issue bottleneck).
// smem bf16: xs[2][32][136] | ws[2][320][40]  (68608 B)
// Epilogue: r11 scatter stores (proven fastest).
// ---------------------------------------------------------------------------
#define XS2 136
#define WS_STR 40
#define QX0 0
#define QX1 4352
#define QW0 8704
#define QW1 21504
#define QKV_SMEM_BF 34304
#define QKV_SMEM_BYTES (QKV_SMEM_BF * 2)   // 68608

__global__ __launch_bounds__(512, 1) void qkv_kernel()
{
    extern __shared__ __align__(16) __nv_bfloat16 smb[];
    const int t    = threadIdx.x;
    const int lane = t & 31;
    const int w    = t >> 5;          // 0..15
    const int g    = lane >> 2;
    const int tg   = lane & 3;
    const int ib   = (w & 7) * 16;    // token tile base (0..112)
    const int oh   = (w >> 3) * 160;  // output half
    const int b    = blockIdx.y;
    const int n0   = blockIdx.x * 128;

    const uint32_t xs_u[2] = { smem_u32(smb + QX0), smem_u32(smb + QX1) };
    const uint32_t ws_u[2] = { smem_u32(smb + QW0), smem_u32(smb + QW1) };

    auto stage = [&](int s, int ch0) {
        {   // x tile [32 ch][128 tok]: 512 cp16
            int row = t >> 4, ck = t & 15;
            cp16(xs_u[s] + (uint32_t)(row*XS2 + ck*8)*2,
                 g_xb + ((size_t)(b*CH + ch0 + row) * NTOK) + n0 + ck*8);
        }
        #pragma unroll
        for (int i = 0; i < 3; i++) {   // W tile [320][32]: 1280 cp16
            int e = t + i*512;
            if (e < 1280) {
                int row = e >> 2, seg = (e & 3) * 8;
                cp16(ws_u[s] + (uint32_t)(row*WS_STR + seg)*2,
                     g_wt + row*256 + ch0 + seg);
            }
        }
        asm volatile("cp.async.commit_group;" ::: "memory");
    };

    float acc[20][4];
    #pragma unroll
    for (int nt = 0; nt < 20; nt++)
        #pragma unroll
        for (int k = 0; k < 4; k++) acc[nt][k] = 0.f;

    stage(0, 0);
    asm volatile("cp.async.wait_group 0;" ::: "memory");
    __syncthreads();

    for (int ks = 0; ks < 8; ks++) {
        const int s = ks & 1;
        if (ks < 7) stage(s ^ 1, (ks+1)*32);   // overlaps compute below

        uint32_t qa[2][4];
        #pragma unroll
        for (int kt = 0; kt < 2; kt++) {
            int chr = kt*16 + (lane & 7) + ((lane >> 4) & 1) * 8;
            int tok = ib + ((lane >> 3) & 1) * 8;
            ldsm_x4_t(qa[kt], xs_u[s] + (uint32_t)(chr*XS2 + tok)*2);
        }
        #pragma unroll
        for (int nt = 0; nt < 20; nt++) {
            uint32_t kb[4];
            int row = oh + nt*8 + (lane & 7);
            int col = (lane >> 3) * 8;
            ldsm_x4(kb, ws_u[s] + (uint32_t)(row*WS_STR + col)*2);
            mma_bf16(acc[nt], qa[0], kb[0], kb[1]);
            mma_bf16(acc[nt], qa[1], kb[2], kb[3]);
        }
        if (ks < 7)
            asm volatile("cp.async.wait_group 0;" ::: "memory");
        __syncthreads();
    }

    // ---- epilogue: r11-style scatter stores (bias folded) ----
    int n_lo = n0 + ib + g;
    #pragma unroll
    for (int nt = 0; nt < 20; nt++) {
        int o = oh + nt*8 + 2*tg;
        float b0 = g_bias[o], b1 = g_bias[o+1];
        uint32_t lo = packbf(acc[nt][0] + b0, acc[nt][1] + b1);
        uint32_t hi = packbf(acc[nt][2] + b0, acc[nt][3] + b1);
        __nv_bfloat16* dst; int ldo, oc;
        if (o < 32)      { dst = g_q; ldo = INTER; oc = o; }
        else if (o < 64) { dst = g_k; ldo = INTER; oc = o - 32; }
        else             { dst = g_v; ldo = CH;    oc = o - 64; }
        dst += (size_t)b * NTOK * ldo;
        *(uint32_t*)&dst[(size_t)(n_lo    ) * ldo + oc] = lo;
        *(uint32_t*)&dst[(size_t)(n_lo + 8) * ldo + oc] = hi;
    }
}

// ---------------------------------------------------------------------------
// Stage 2: bf16 TC flash attention (exact r7 / 178.8us version, unchanged).
// Q-tile 128, 512 threads, 16 warps; j-tile 64, double-buffered.
// smem bf16: Q[128][40] | K[2][64][40] | V[2][64][264] | P[128][72] | lsum f32
// ---------------------------------------------------------------------------
#define SQB 40
#define SVB 264
#define SPB 72
#define OFFQ 0
#define OFFK 5120
#define OFFV 10240
#define OFFP 44032
#define KBUF 2560
#define VBUF 16896
#define ATT_SMEM_BF 53248
#define ATT_SMEM_BYTES (ATT_SMEM_BF*2 + 1024)   // 107520

__global__ __launch_bounds__(512, 1) void attn_kernel(
    const float* __restrict__ x, const float* __restrict__ gamma_p,
    float* __restrict__ out)
{
    extern __shared__ __align__(16) __nv_bfloat16 smb[];
    float* lsum = (float*)(smb + ATT_SMEM_BF);

    const int t    = threadIdx.x;
    const int lane = t & 31;
    const int w    = t >> 5;        // 0..15
    const int g    = lane >> 2;
    const int tg   = lane & 3;
    const int iw   = w & 7;
    const int ib   = iw * 16;       // i-tile base (0..112)
    const int half = w >> 3;
    const int cb   = half * 128;
    const int jh   = half * 32;
    const int b    = blockIdx.y;
    const int i0   = blockIdx.x * 128;

    const uint32_t q_u  = smem_u32(smb + OFFQ);
    const uint32_t k_u0 = smem_u32(smb + OFFK);
    const uint32_t v_u0 = smem_u32(smb + OFFV);
    const uint32_t p_u  = smem_u32(smb + OFFP);

    auto stage = [&](int s, int j0) {
        if (t < 256) {   // K tile [64][32]
            int row = t >> 2, c = t & 3;
            cp16(k_u0 + (uint32_t)(s*KBUF + row*SQB + c*8)*2,
                 g_k + ((size_t)(b*NTOK + j0 + row) * INTER) + c*8);
        }
        {   // V tile [64][256]: row = t>>3, 4 cp16 each
            int row = t >> 3, cs = t & 7;
            const __nv_bfloat16* vsrc = g_v + ((size_t)(b*NTOK + j0 + row) * CH);
            uint32_t vdst = v_u0 + (uint32_t)(s*VBUF + row*SVB)*2;
            #pragma unroll
            for (int k = 0; k < 4; k++) {
                int ch = (cs + 8*k) * 8;
                cp16(vdst + ch*2, vsrc + ch);
            }
        }
        asm volatile("cp.async.commit_group;" ::: "memory");
    };

    {   // prologue: Q [128][32] (one group), then tile 0
        int row = t >> 2, c = t & 3;
        cp16(q_u + (uint32_t)(row*SQB + c*8)*2,
             g_q + ((size_t)(b*NTOK + i0 + row) * INTER) + c*8);
        asm volatile("cp.async.commit_group;" ::: "memory");
    }
    stage(0, 0);
    asm volatile("cp.async.wait_group 1;" ::: "memory");   // Q landed
    __syncthreads();                                       // Q visible

    uint32_t qa[2][4];
    #pragma unroll
    for (int kt = 0; kt < 2; kt++) {
        int row = ib + (lane & 7) + ((lane >> 3) & 1) * 8;
        int col = kt*16 + ((lane >> 4) & 1) * 8;
        ldsm_x4(qa[kt], q_u + (uint32_t)(row*SQB + col)*2);
    }

    float acc[16][4];
    #pragma unroll
    for (int nt = 0; nt < 16; nt++)
        #pragma unroll
        for (int k = 0; k < 4; k++) acc[nt][k] = 0.f;
    float l0 = 0.f, l1 = 0.f;

    for (int jt = 0; jt < 64; jt++) {
        const int s = jt & 1;

        __syncthreads();   // [A] prev iter fully done: buf s^1 and P free
        if (jt < 63) {
            stage(s ^ 1, (jt + 1) * 64);
            asm volatile("cp.async.wait_group 1;" ::: "memory");  // buf s landed
        } else {
            asm volatile("cp.async.wait_group 0;" ::: "memory");
        }
        __syncthreads();   // [V] buf s visible to ALL threads

        const uint32_t k_u = k_u0 + (uint32_t)(s*KBUF)*2;
        const uint32_t v_u = v_u0 + (uint32_t)(s*VBUF)*2;

        // ---- QK^T on this warp's j-half: S[16][32] (log2 units) ----
        float sfr[4][4];
        #pragma unroll
        for (int j8 = 0; j8 < 4; j8++) {
            sfr[j8][0] = sfr[j8][1] = sfr[j8][2] = sfr[j8][3] = 0.f;
            uint32_t kb[4];
            int row = jh + j8*8 + (lane & 7);
            int col = (lane >> 3) * 8;
            ldsm_x4(kb, k_u + (uint32_t)(row*SQB + col)*2);
            mma_bf16(sfr[j8], qa[0], kb[0], kb[1]);
            mma_bf16(sfr[j8], qa[1], kb[2], kb[3]);
        }

        // ---- exp2, accumulate l, store P (bf16) ----
        #pragma unroll
        for (int j8 = 0; j8 < 4; j8++) {
            float p0 = ex2(sfr[j8][0]), p1 = ex2(sfr[j8][1]);
            float p2 = ex2(sfr[j8][2]), p3 = ex2(sfr[j8][3]);
            l0 += p0 + p1;
            l1 += p2 + p3;
            int col = jh + j8*8 + 2*tg;
            *(uint32_t*)(smb + OFFP + (ib + g    )*SPB + col) = packbf(p0, p1);
            *(uint32_t*)(smb + OFFP + (ib + 8 + g)*SPB + col) = packbf(p2, p3);
        }

        // [B] pair barrier: warps {iw, iw+8} both finished their P half.
        asm volatile("bar.sync %0, 64;" :: "r"(1 + iw) : "memory");

        // ---- PV: O[16][128] += P[16][64] x V[64][128] ----
        #pragma unroll
        for (int kt = 0; kt < 4; kt++) {
            uint32_t pa[4];
            {
                int row = ib + (lane & 7) + ((lane >> 3) & 1) * 8;
                int col = kt*16 + ((lane >> 4) & 1) * 8;
                ldsm_x4(pa, p_u + (uint32_t)(row*SPB + col)*2);
            }
            #pragma unroll
            for (int np = 0; np < 8; np++) {
                uint32_t vb[4];
                int row = kt*16 + ((lane >> 3) & 1)*8 + (lane & 7);
                int col = cb + (np*2 + (lane >> 4)) * 8;
                ldsm_x4_t(vb, v_u + (uint32_t)(row*SVB + col)*2);
                mma_bf16(acc[2*np    ], pa, vb[0], vb[1]);
                mma_bf16(acc[2*np + 1], pa, vb[2], vb[3]);
            }
        }
    }

    // ---- combine l across quad lanes + across j-half warps ----
    l0 += __shfl_xor_sync(0xffffffffu, l0, 1);
    l0 += __shfl_xor_sync(0xffffffffu, l0, 2);
    l1 += __shfl_xor_sync(0xffffffffu, l1, 1);
    l1 += __shfl_xor_sync(0xffffffffu, l1, 2);
    if (tg == 0) {
        lsum[(ib + g    )*2 + half] = l0;
        lsum[(ib + 8 + g)*2 + half] = l1;
    }
    __syncthreads();
    float li0 = 1.f / (lsum[(ib + g    )*2] + lsum[(ib + g    )*2 + 1]);
    float li1 = 1.f / (lsum[(ib + 8 + g)*2] + lsum[(ib + 8 + g)*2 + 1]);
    #pragma unroll
    for (int nt = 0; nt < 16; nt++) {
        acc[nt][0] *= li0; acc[nt][1] *= li0;
        acc[nt][2] *= li1; acc[nt][3] *= li1;
    }

    // ---- epilogue: two 64-query halves through smem transpose ----
    const float gmm = gamma_p[0];
    float (*ot)[68] = (float (*)[68])smb;   // [256][68] fp32; lsum is beyond
    for (int h = 0; h < 2; h++) {
        __syncthreads();
        if ((iw >> 2) == h) {
            int il = (ib & 63) + g;   // 0..63 within half
            #pragma unroll
            for (int nt = 0; nt < 16; nt++) {
                int c = cb + nt*8 + 2*tg;
                ot[c  ][il  ] = acc[nt][0];
                ot[c+1][il  ] = acc[nt][1];
                ot[c  ][il+8] = acc[nt][2];
                ot[c+1][il+8] = acc[nt][3];
            }
        }
        __syncthreads();
        {   // 512 threads: c = t>>1, token segment (t&1)*32 (8 float4)
            int c = t >> 1, seg = (t & 1) * 32;
            size_t base = ((size_t)(b*CH + c)) * NTOK + i0 + h*64 + seg;
            const float4* xp = (const float4*)(x + base);
            float4* op = (float4*)(out + base);
            #pragma unroll
            for (int i4 = 0; i4 < 8; i4++) {
                float4 xv = xp[i4];
                float4 r4;
                r4.x = gmm * ot[c][seg + i4*4 + 0] + xv.x;
                r4.y = gmm * ot[c][seg + i4*4 + 1] + xv.y;
                r4.z = gmm * ot[c][seg + i4*4 + 2] + xv.z;
                r4.w = gmm * ot[c][seg + i4*4 + 3] + xv.w;
                op[i4] = r4;
            }
        }
    }
}

// ---------------------------------------------------------------------------
extern "C" void kernel_launch(void* const* d_in, const int* in_sizes, int n_in,
                              void* d_out, int out_size)
{
    const float* x  = (const float*)d_in[0];
    const float* Wq = (const float*)d_in[1];
    const float* bq = (const float*)d_in[2];
    const float* Wk = (const float*)d_in[3];
    const float* bk = (const float*)d_in[4];
    const float* Wv = (const float*)d_in[5];
    const float* bv = (const float*)d_in[6];
    const float* gm = (const float*)d_in[7];
    float* out = (float*)d_out;

    cudaFuncSetAttribute(qkv_kernel,  cudaFuncAttributeMaxDynamicSharedMemorySize, QKV_SMEM_BYTES);
    cudaFuncSetAttribute(attn_kernel, cudaFuncAttributeMaxDynamicSharedMemorySize, ATT_SMEM_BYTES);

    preconv_kernel<<<80 + 2048, 256>>>(x, Wq, bq, Wk, bk, Wv, bv);

    dim3 g1(NTOK / 128, BATCH);
    qkv_kernel<<<g1, 512, QKV_SMEM_BYTES>>>();

    dim3 g2(NTOK / 128, BATCH);
    attn_kernel<<<g2, 512, ATT_SMEM_BYTES>>>(x, gm, out);
}